// round 11
// baseline (speedup 1.0000x reference)
#include <cuda_runtime.h>
#include <cuda_fp16.h>
#include <math.h>

#define NN 100000
#define NE 1600000
#define FIN 128
#define FE 16
#define HH 64
#define TT 32
#define SCAN_B 1024
#define NBLK ((NN + SCAN_B - 1) / SCAN_B)   // 98

// ---------------- scratch (device globals; no runtime alloc) ----------------
__device__ __align__(16) __half2 g_h16[NN * 32]; // h in fp16, 64 halves/node
__device__ __align__(16) float g_feat[NN * HH];  // layer-1 output (relu'd)
__device__ float g_hs[NN];
__device__ float g_hd[NN];
__device__ int   g_degi[NN];
__device__ int   g_row[NN + 1];
__device__ int   g_cursor[NN];
__device__ int   g_bsum[NBLK];
__device__ __align__(16) int4 g_ecsr[NE];        // {src, cet0, cet1, dst} CSR order
__device__ float g_weae[2][FE];

__global__ void k_weae(const float* We1, const float* ae1,
                       const float* We2, const float* ae2) {
    int t = threadIdx.x;
    if (t < FE) {
        float s = 0.f;
        for (int h = 0; h < HH; h++) s += We1[t * HH + h] * ae1[h];
        g_weae[0][t] = s;
    } else if (t < 2 * FE) {
        int f = t - FE;
        float s = 0.f;
        for (int h = 0; h < HH; h++) s += We2[f * HH + h] * ae2[h];
        g_weae[1][f] = s;
    }
}

__global__ void k_zero_pre() {
    int idx = blockIdx.x * blockDim.x + threadIdx.x;
    if (idx < NN) g_degi[idx] = 0;
    if (idx == 0) g_row[NN] = NE;
}

__global__ void k_deg(const int* __restrict__ dst) {
    int e = blockIdx.x * blockDim.x + threadIdx.x;
    if (e < NE) atomicAdd(&g_degi[dst[e]], 1);
}

__global__ void k_scan_part() {
    __shared__ int wsum[32];
    int tid = threadIdx.x, lane = tid & 31, wid = tid >> 5;
    int idx = blockIdx.x * SCAN_B + tid;
    int v = (idx < NN) ? g_degi[idx] : 0;
    int x = v;
#pragma unroll
    for (int o = 1; o < 32; o <<= 1) { int y = __shfl_up_sync(~0u, x, o); if (lane >= o) x += y; }
    if (lane == 31) wsum[wid] = x;
    __syncthreads();
    if (wid == 0) {
        int s = wsum[lane];
#pragma unroll
        for (int o = 1; o < 32; o <<= 1) { int y = __shfl_up_sync(~0u, s, o); if (lane >= o) s += y; }
        wsum[lane] = s;
    }
    __syncthreads();
    int off = wid ? wsum[wid - 1] : 0;
    if (idx < NN) g_row[idx] = x - v + off;
    if (tid == SCAN_B - 1) g_bsum[blockIdx.x] = off + x;
}

__global__ void k_scan_fin() {
    __shared__ int sh[NBLK + 1];
    int tid = threadIdx.x;
    if (tid < NBLK) sh[tid + 1] = g_bsum[tid];
    if (tid == 0) sh[0] = 0;
    __syncthreads();
    if (tid == 0) {
#pragma unroll 8
        for (int i = 1; i < NBLK; i++) sh[i + 1] += sh[i];
    }
    __syncthreads();
    int idx = blockIdx.x * SCAN_B + tid;
    if (idx < NN) {
        int r = g_row[idx] + sh[blockIdx.x];
        g_row[idx] = r;
        g_cursor[idx] = r;
    }
}

__global__ void k_edge_pre(const float* __restrict__ ea, const int* __restrict__ src,
                           const int* __restrict__ dst) {
    int e = blockIdx.x * blockDim.x + threadIdx.x;
    if (e >= NE) return;
    int d = dst[e];
    const float4* v = (const float4*)(ea + (size_t)e * FE);
    float4 a0 = v[0], a1 = v[1], a2 = v[2], a3 = v[3];
    float av[16] = {a0.x, a0.y, a0.z, a0.w, a1.x, a1.y, a1.z, a1.w,
                    a2.x, a2.y, a2.z, a2.w, a3.x, a3.y, a3.z, a3.w};
    float s0 = 0.f, s1 = 0.f;
#pragma unroll
    for (int f = 0; f < FE; f++) {
        s0 += av[f] * g_weae[0][f];
        s1 += av[f] * g_weae[1][f];
    }
    int pos = atomicAdd(&g_cursor[d], 1);
    int4 ent;
    ent.x = src[e];
    ent.y = __float_as_int(s0);
    ent.z = __float_as_int(s1);
    ent.w = d;
    g_ecsr[pos] = ent;
}

// h = x @ W, 64x64 tile, 4x4 per thread, 256 threads (verified 67-70us config).
template <int DIN>
__global__ __launch_bounds__(256) void k_gemm(const float* __restrict__ x,
                                              const float* __restrict__ W,
                                              const float* __restrict__ a_s,
                                              const float* __restrict__ a_d) {
    __shared__ __align__(16) float xs[DIN * 68];
    __shared__ __align__(16) float Ws[DIN * 64];
    int tid = threadIdx.x;
    int row0 = blockIdx.x * 64;
    for (int i = tid; i < DIN * 64; i += 256) Ws[i] = W[i];
    for (int i = tid; i < 64 * DIN; i += 256) {
        int r = i / DIN, k = i % DIN;
        int rr = row0 + r;
        xs[k * 68 + r] = (rr < NN) ? x[(size_t)rr * DIN + k] : 0.f;
    }
    __syncthreads();
    int rg = tid >> 4, cg = tid & 15;
    float acc[4][4] = {};
#pragma unroll 4
    for (int k = 0; k < DIN; k++) {
        float4 xv = *(const float4*)&xs[k * 68 + 4 * rg];
        float4 wv = *(const float4*)&Ws[k * 64 + 4 * cg];
        acc[0][0] = fmaf(xv.x, wv.x, acc[0][0]);
        acc[0][1] = fmaf(xv.x, wv.y, acc[0][1]);
        acc[0][2] = fmaf(xv.x, wv.z, acc[0][2]);
        acc[0][3] = fmaf(xv.x, wv.w, acc[0][3]);
        acc[1][0] = fmaf(xv.y, wv.x, acc[1][0]);
        acc[1][1] = fmaf(xv.y, wv.y, acc[1][1]);
        acc[1][2] = fmaf(xv.y, wv.z, acc[1][2]);
        acc[1][3] = fmaf(xv.y, wv.w, acc[1][3]);
        acc[2][0] = fmaf(xv.z, wv.x, acc[2][0]);
        acc[2][1] = fmaf(xv.z, wv.y, acc[2][1]);
        acc[2][2] = fmaf(xv.z, wv.z, acc[2][2]);
        acc[2][3] = fmaf(xv.z, wv.w, acc[2][3]);
        acc[3][0] = fmaf(xv.w, wv.x, acc[3][0]);
        acc[3][1] = fmaf(xv.w, wv.y, acc[3][1]);
        acc[3][2] = fmaf(xv.w, wv.z, acc[3][2]);
        acc[3][3] = fmaf(xv.w, wv.w, acc[3][3]);
    }
    float myas[4], myad[4];
#pragma unroll
    for (int j = 0; j < 4; j++) { myas[j] = a_s[4 * cg + j]; myad[j] = a_d[4 * cg + j]; }
#pragma unroll
    for (int i = 0; i < 4; i++) {
        int row = row0 + 4 * rg + i;
        float hs = acc[i][0] * myas[0] + acc[i][1] * myas[1] +
                   acc[i][2] * myas[2] + acc[i][3] * myas[3];
        float hd = acc[i][0] * myad[0] + acc[i][1] * myad[1] +
                   acc[i][2] * myad[2] + acc[i][3] * myad[3];
#pragma unroll
        for (int o = 1; o < 16; o <<= 1) {
            hs += __shfl_xor_sync(~0u, hs, o);
            hd += __shfl_xor_sync(~0u, hd, o);
        }
        if (row < NN) {
            if (cg == 0) { g_hs[row] = hs; g_hd[row] = hd; }
            __half2* hp = &g_h16[(size_t)row * 32 + 2 * cg];
            hp[0] = __floats2half2_rn(acc[i][0], acc[i][1]);
            hp[1] = __floats2half2_rn(acc[i][2], acc[i][3]);
        }
    }
}

// TWO warps per dst node; each handles half the edge range; smem combine.
// Gather: 8 lanes x 16B per h-row -> 4 edges per LDG.128.
// NN % 4 == 0 so every block's 4 node slots are valid (no early returns).
template <int L, bool FUSE>
__global__ __launch_bounds__(256) void k_aggregate(const float* __restrict__ b,
                                                   const float* __restrict__ Wc1,
                                                   const float* __restrict__ bc1,
                                                   const float* __restrict__ Wc2,
                                                   const float* __restrict__ bc2,
                                                   float* __restrict__ out) {
    __shared__ float s_acc[4][66];   // per node: 64 acc cols + z + cs
    int wid = threadIdx.x >> 5;      // 0..7
    int lane = threadIdx.x & 31;
    int ns = wid >> 1;               // node slot 0..3
    int half = wid & 1;
    int node = blockIdx.x * 4 + ns;

    int beg = g_row[node], end = g_row[node + 1];
    int deg = end - beg;
    int cnt0 = (deg + 1) >> 1;
    int mybeg = half ? beg + cnt0 : beg;
    int myend = half ? end : beg + cnt0;

    float hd_d = g_hd[node];
    int q = lane >> 3;     // edge slot 0..3
    int sub = lane & 7;    // column octet 0..7
    const __half* hbase = (const __half*)g_h16;
    float acc[8] = {};
    float z = 0.f, cs = 0.f;

    for (int base = mybeg; base < myend; base += 32) {
        int i = base + lane;
        bool valid = i < myend;
        int4 ent = valid ? g_ecsr[i] : make_int4(0, 0, 0, 0);
        int s = ent.x;
        float c = __int_as_float((L == 0) ? ent.y : ent.z);
        float p = 0.f;
        if (valid) {
            float a = g_hs[s] + hd_d + c;
            a = (a > 0.f) ? a : 0.2f * a;
            p = __expf(a);
            z += p;
            cs += c;
        }
        int cnt = min(32, myend - base);
        for (int j = 0; j < cnt; j += 4) {
            int idx = j + q;
            bool vq = idx < cnt;
            int sel = vq ? idx : 0;
            int sj = __shfl_sync(~0u, s, sel);
            float pj = __shfl_sync(~0u, p, sel);
            if (!vq) pj = 0.f;
            uint4 raw = *(const uint4*)(hbase + ((size_t)sj << 6) + (sub << 3));
            float2 f0 = __half22float2(*(const __half2*)&raw.x);
            float2 f1 = __half22float2(*(const __half2*)&raw.y);
            float2 f2 = __half22float2(*(const __half2*)&raw.z);
            float2 f3 = __half22float2(*(const __half2*)&raw.w);
            acc[0] = fmaf(pj, f0.x, acc[0]);
            acc[1] = fmaf(pj, f0.y, acc[1]);
            acc[2] = fmaf(pj, f1.x, acc[2]);
            acc[3] = fmaf(pj, f1.y, acc[3]);
            acc[4] = fmaf(pj, f2.x, acc[4]);
            acc[5] = fmaf(pj, f2.y, acc[5]);
            acc[6] = fmaf(pj, f3.x, acc[6]);
            acc[7] = fmaf(pj, f3.y, acc[7]);
        }
    }
    // intra-warp reductions
#pragma unroll
    for (int o = 16; o; o >>= 1) {
        z += __shfl_xor_sync(0xffffffffu, z, o);
        cs += __shfl_xor_sync(0xffffffffu, cs, o);
    }
#pragma unroll
    for (int t = 0; t < 8; t++) {
        acc[t] += __shfl_xor_sync(~0u, acc[t], 8);
        acc[t] += __shfl_xor_sync(~0u, acc[t], 16);
    }
    // cross-warp combine via smem: half 1 publishes, half 0 consumes
    if (half == 1) {
        if (lane < 8) {
#pragma unroll
            for (int t = 0; t < 8; t++) s_acc[ns][8 * lane + t] = acc[t];
        } else if (lane == 8) {
            s_acc[ns][64] = z;
        } else if (lane == 9) {
            s_acc[ns][65] = cs;
        }
    }
    __syncthreads();
    if (half == 1) return;

#pragma unroll
    for (int t = 0; t < 8; t++) acc[t] += s_acc[ns][8 * sub + t];
    z += s_acc[ns][64];
    cs += s_acc[ns][65];

    // self loop
    float eloop = cs / fmaxf((float)deg, 1.f);
    float al = g_hs[node] + hd_d + eloop;
    al = (al > 0.f) ? al : 0.2f * al;
    float pl = __expf(al);
    z += pl;
    {
        uint4 raw = *(const uint4*)(hbase + ((size_t)node << 6) + (sub << 3));
        float2 f0 = __half22float2(*(const __half2*)&raw.x);
        float2 f1 = __half22float2(*(const __half2*)&raw.y);
        float2 f2 = __half22float2(*(const __half2*)&raw.z);
        float2 f3 = __half22float2(*(const __half2*)&raw.w);
        acc[0] = fmaf(pl, f0.x, acc[0]);
        acc[1] = fmaf(pl, f0.y, acc[1]);
        acc[2] = fmaf(pl, f1.x, acc[2]);
        acc[3] = fmaf(pl, f1.y, acc[3]);
        acc[4] = fmaf(pl, f2.x, acc[4]);
        acc[5] = fmaf(pl, f2.y, acc[5]);
        acc[6] = fmaf(pl, f3.x, acc[6]);
        acc[7] = fmaf(pl, f3.y, acc[7]);
    }
    float inv = 1.f / z;
    float fv[8];
#pragma unroll
    for (int t = 0; t < 8; t++)
        fv[t] = fmaxf(fmaf(acc[t], inv, b[8 * sub + t]), 0.f);

    if (!FUSE) {
        if (lane < 8) {
            float4* fp = (float4*)(g_feat + (size_t)node * HH + 8 * sub);
            fp[0] = make_float4(fv[0], fv[1], fv[2], fv[3]);
            fp[1] = make_float4(fv[4], fv[5], fv[6], fv[7]);
        }
    } else {
        float accm = bc1[lane];
#pragma unroll
        for (int k = 0; k < 64; k++)
            accm = fmaf(__shfl_sync(~0u, fv[k & 7], k >> 3), Wc1[k * 32 + lane], accm);
        float hid = fmaxf(accm, 0.f);
        float lg = bc2[lane];
#pragma unroll
        for (int jj = 0; jj < 32; jj++)
            lg = fmaf(__shfl_sync(~0u, hid, jj), Wc2[jj * TT + lane], lg);
        out[(size_t)node * TT + lane] = lg;
    }
}

extern "C" void kernel_launch(void* const* d_in, const int* in_sizes, int n_in,
                              void* d_out, int out_size) {
    const float* x   = (const float*)d_in[0];
    const int*   ei  = (const int*)d_in[1];
    const float* ea  = (const float*)d_in[2];
    const float* W1  = (const float*)d_in[3];
    const float* as1 = (const float*)d_in[4];
    const float* ad1 = (const float*)d_in[5];
    const float* We1 = (const float*)d_in[6];
    const float* ae1 = (const float*)d_in[7];
    const float* b1  = (const float*)d_in[8];
    const float* W2  = (const float*)d_in[9];
    const float* as2 = (const float*)d_in[10];
    const float* ad2 = (const float*)d_in[11];
    const float* We2 = (const float*)d_in[12];
    const float* ae2 = (const float*)d_in[13];
    const float* b2  = (const float*)d_in[14];
    const float* Wc1 = (const float*)d_in[15];
    const float* bc1 = (const float*)d_in[16];
    const float* Wc2 = (const float*)d_in[17];
    const float* bc2 = (const float*)d_in[18];
    float* out = (float*)d_out;

    const int* src = ei;
    const int* dst = ei + NE;

    float* d_feat;
    cudaGetSymbolAddress((void**)&d_feat, g_feat);

    static cudaStream_t s2 = nullptr;
    static cudaEvent_t evFork = nullptr, evJoin = nullptr;
    if (!s2) {
        cudaStreamCreateWithFlags(&s2, cudaStreamNonBlocking);
        cudaEventCreateWithFlags(&evFork, cudaEventDisableTiming);
        cudaEventCreateWithFlags(&evJoin, cudaEventDisableTiming);
    }

    cudaEventRecord(evFork, 0);
    cudaStreamWaitEvent(s2, evFork, 0);

    k_weae<<<1, 32>>>(We1, ae1, We2, ae2);
    k_zero_pre<<<(NN + 255) / 256, 256>>>();
    k_deg<<<(NE + 255) / 256, 256>>>(dst);

    k_gemm<FIN><<<(NN + 63) / 64, 256, 0, s2>>>(x, W1, as1, ad1);   // 4th launch (profiled)
    cudaEventRecord(evJoin, s2);

    k_scan_part<<<NBLK, SCAN_B>>>();
    k_scan_fin<<<NBLK, SCAN_B>>>();
    k_edge_pre<<<(NE + 255) / 256, 256>>>(ea, src, dst);

    cudaStreamWaitEvent(0, evJoin, 0);

    // ---- layer 1 ----
    k_aggregate<0, false><<<NN / 4, 256>>>(b1, nullptr, nullptr, nullptr, nullptr, nullptr);

    // ---- layer 2 (+ fused classifier) ----
    k_gemm<HH><<<(NN + 63) / 64, 256>>>(d_feat, W2, as2, ad2);
    k_aggregate<1, true><<<NN / 4, 256>>>(b2, Wc1, bc1, Wc2, bc2, out);
}

// round 12
// speedup vs baseline: 1.0083x; 1.0083x over previous
#include <cuda_runtime.h>
#include <cuda_fp16.h>
#include <math.h>

#define NN 100000
#define NE 1600000
#define FIN 128
#define FE 16
#define HH 64
#define TT 32
#define SCAN_B 1024
#define NBLK ((NN + SCAN_B - 1) / SCAN_B)   // 98

// ---------------- scratch (device globals; no runtime alloc) ----------------
__device__ __align__(16) __half2 g_h16[NN * 32]; // h in fp16, 64 halves/node
__device__ __align__(16) float g_feat[NN * HH];  // layer-1 output (relu'd)
__device__ float g_hs[NN];
__device__ float g_hd[NN];
__device__ int   g_degi[NN];
__device__ int   g_row[NN + 1];
__device__ int   g_cursor[NN];
__device__ volatile int g_bpub[NBLK];            // lookback publications (total+1)
__device__ __align__(16) int4 g_ecsr[NE];        // {src, cet0, cet1, pad} CSR order
__device__ float g_weae[2][FE];

// init: weae + zero degi + zero publications + row[NN]
__global__ void k_init(const float* We1, const float* ae1,
                       const float* We2, const float* ae2) {
    int idx = blockIdx.x * blockDim.x + threadIdx.x;
    if (idx < NN) g_degi[idx] = 0;
    if (idx < NBLK) g_bpub[idx] = 0;
    if (idx == 0) g_row[NN] = NE;
    if (blockIdx.x == 0) {
        int t = threadIdx.x;
        if (t < FE) {
            float s = 0.f;
            for (int h = 0; h < HH; h++) s += We1[t * HH + h] * ae1[h];
            g_weae[0][t] = s;
        } else if (t < 2 * FE) {
            int f = t - FE;
            float s = 0.f;
            for (int h = 0; h < HH; h++) s += We2[f * HH + h] * ae2[h];
            g_weae[1][f] = s;
        }
    }
}

__global__ void k_deg(const int* __restrict__ dst) {
    int e = blockIdx.x * blockDim.x + threadIdx.x;
    if (e < NE) atomicAdd(&g_degi[dst[e]], 1);
}

// single-kernel scan: block-local scan + publish + spin on predecessors.
// 98 blocks (<=148 SMs, all co-resident); block b waits only on blocks < b.
__global__ void k_scan_lb() {
    __shared__ int wsum[32];
    __shared__ int svals[NBLK];
    __shared__ int prevsum;
    int tid = threadIdx.x, lane = tid & 31, wid = tid >> 5;
    int b = blockIdx.x;
    int idx = b * SCAN_B + tid;
    int v = (idx < NN) ? g_degi[idx] : 0;
    int x = v;
#pragma unroll
    for (int o = 1; o < 32; o <<= 1) { int y = __shfl_up_sync(~0u, x, o); if (lane >= o) x += y; }
    if (lane == 31) wsum[wid] = x;
    __syncthreads();
    if (wid == 0) {
        int s = wsum[lane];
#pragma unroll
        for (int o = 1; o < 32; o <<= 1) { int y = __shfl_up_sync(~0u, s, o); if (lane >= o) s += y; }
        wsum[lane] = s;
    }
    __syncthreads();
    int off = wid ? wsum[wid - 1] : 0;
    // publish block total ASAP (done by last warp; independent of warp-0 spin)
    if (tid == SCAN_B - 1) {
        atomicExch((int*)&g_bpub[b], off + x + 1);
    }
    // spin for predecessors only (block 0 waits on none)
    if (tid < b) {
        int vv;
        do { vv = g_bpub[tid]; } while (vv == 0);
        svals[tid] = vv - 1;
    }
    __syncthreads();
    if (tid == 0) {
        int s = 0;
        for (int i = 0; i < b; i++) s += svals[i];
        prevsum = s;
    }
    __syncthreads();
    if (idx < NN) {
        int r = x - v + off + prevsum;
        g_row[idx] = r;
        g_cursor[idx] = r;
    }
}

__global__ void k_edge_pre(const float* __restrict__ ea, const int* __restrict__ src,
                           const int* __restrict__ dst) {
    int e = blockIdx.x * blockDim.x + threadIdx.x;
    if (e >= NE) return;
    int d = dst[e];
    const float4* v = (const float4*)(ea + (size_t)e * FE);
    float4 a0 = v[0], a1 = v[1], a2 = v[2], a3 = v[3];
    float av[16] = {a0.x, a0.y, a0.z, a0.w, a1.x, a1.y, a1.z, a1.w,
                    a2.x, a2.y, a2.z, a2.w, a3.x, a3.y, a3.z, a3.w};
    float s0 = 0.f, s1 = 0.f;
#pragma unroll
    for (int f = 0; f < FE; f++) {
        s0 += av[f] * g_weae[0][f];
        s1 += av[f] * g_weae[1][f];
    }
    int pos = atomicAdd(&g_cursor[d], 1);
    int4 ent;
    ent.x = src[e];
    ent.y = __float_as_int(s0);
    ent.z = __float_as_int(s1);
    ent.w = 0;
    g_ecsr[pos] = ent;
}

// h = x @ W, 64x64 tile, 4x4 per thread, 256 threads (verified 67us config).
template <int DIN>
__global__ __launch_bounds__(256) void k_gemm(const float* __restrict__ x,
                                              const float* __restrict__ W,
                                              const float* __restrict__ a_s,
                                              const float* __restrict__ a_d) {
    __shared__ __align__(16) float xs[DIN * 68];
    __shared__ __align__(16) float Ws[DIN * 64];
    int tid = threadIdx.x;
    int row0 = blockIdx.x * 64;
    for (int i = tid; i < DIN * 64; i += 256) Ws[i] = W[i];
    for (int i = tid; i < 64 * DIN; i += 256) {
        int r = i / DIN, k = i % DIN;
        int rr = row0 + r;
        xs[k * 68 + r] = (rr < NN) ? x[(size_t)rr * DIN + k] : 0.f;
    }
    __syncthreads();
    int rg = tid >> 4, cg = tid & 15;
    float acc[4][4] = {};
#pragma unroll 4
    for (int k = 0; k < DIN; k++) {
        float4 xv = *(const float4*)&xs[k * 68 + 4 * rg];
        float4 wv = *(const float4*)&Ws[k * 64 + 4 * cg];
        acc[0][0] = fmaf(xv.x, wv.x, acc[0][0]);
        acc[0][1] = fmaf(xv.x, wv.y, acc[0][1]);
        acc[0][2] = fmaf(xv.x, wv.z, acc[0][2]);
        acc[0][3] = fmaf(xv.x, wv.w, acc[0][3]);
        acc[1][0] = fmaf(xv.y, wv.x, acc[1][0]);
        acc[1][1] = fmaf(xv.y, wv.y, acc[1][1]);
        acc[1][2] = fmaf(xv.y, wv.z, acc[1][2]);
        acc[1][3] = fmaf(xv.y, wv.w, acc[1][3]);
        acc[2][0] = fmaf(xv.z, wv.x, acc[2][0]);
        acc[2][1] = fmaf(xv.z, wv.y, acc[2][1]);
        acc[2][2] = fmaf(xv.z, wv.z, acc[2][2]);
        acc[2][3] = fmaf(xv.z, wv.w, acc[2][3]);
        acc[3][0] = fmaf(xv.w, wv.x, acc[3][0]);
        acc[3][1] = fmaf(xv.w, wv.y, acc[3][1]);
        acc[3][2] = fmaf(xv.w, wv.z, acc[3][2]);
        acc[3][3] = fmaf(xv.w, wv.w, acc[3][3]);
    }
    float myas[4], myad[4];
#pragma unroll
    for (int j = 0; j < 4; j++) { myas[j] = a_s[4 * cg + j]; myad[j] = a_d[4 * cg + j]; }
#pragma unroll
    for (int i = 0; i < 4; i++) {
        int row = row0 + 4 * rg + i;
        float hs = acc[i][0] * myas[0] + acc[i][1] * myas[1] +
                   acc[i][2] * myas[2] + acc[i][3] * myas[3];
        float hd = acc[i][0] * myad[0] + acc[i][1] * myad[1] +
                   acc[i][2] * myad[2] + acc[i][3] * myad[3];
#pragma unroll
        for (int o = 1; o < 16; o <<= 1) {
            hs += __shfl_xor_sync(~0u, hs, o);
            hd += __shfl_xor_sync(~0u, hd, o);
        }
        if (row < NN) {
            if (cg == 0) { g_hs[row] = hs; g_hd[row] = hd; }
            __half2* hp = &g_h16[(size_t)row * 32 + 2 * cg];
            hp[0] = __floats2half2_rn(acc[i][0], acc[i][1]);
            hp[1] = __floats2half2_rn(acc[i][2], acc[i][3]);
        }
    }
}

// One warp per dst node (302us-verified R8 config, unchanged).
template <int L, bool FUSE>
__global__ __launch_bounds__(256) void k_aggregate(const float* __restrict__ b,
                                                   const float* __restrict__ Wc1,
                                                   const float* __restrict__ bc1,
                                                   const float* __restrict__ Wc2,
                                                   const float* __restrict__ bc2,
                                                   float* __restrict__ out) {
    int node = blockIdx.x * 8 + (threadIdx.x >> 5);
    int lane = threadIdx.x & 31;
    if (node >= NN) return;
    int beg = g_row[node], end = g_row[node + 1];
    float hd_d = g_hd[node];
    int q = lane >> 3;
    int sub = lane & 7;
    const __half* hbase = (const __half*)g_h16;
    float acc[8] = {};
    float z = 0.f, cs = 0.f;

    for (int base = beg; base < end; base += 32) {
        int i = base + lane;
        bool valid = i < end;
        int4 ent = valid ? g_ecsr[i] : make_int4(0, 0, 0, 0);
        int s = ent.x;
        float c = __int_as_float((L == 0) ? ent.y : ent.z);
        float p = 0.f;
        if (valid) {
            float a = g_hs[s] + hd_d + c;
            a = (a > 0.f) ? a : 0.2f * a;
            p = __expf(a);
            z += p;
            cs += c;
        }
        int cnt = min(32, end - base);
        for (int j = 0; j < cnt; j += 4) {
            int idx = j + q;
            bool vq = idx < cnt;
            int sel = vq ? idx : 0;
            int sj = __shfl_sync(~0u, s, sel);
            float pj = __shfl_sync(~0u, p, sel);
            if (!vq) pj = 0.f;
            uint4 raw = *(const uint4*)(hbase + ((size_t)sj << 6) + (sub << 3));
            float2 f0 = __half22float2(*(const __half2*)&raw.x);
            float2 f1 = __half22float2(*(const __half2*)&raw.y);
            float2 f2 = __half22float2(*(const __half2*)&raw.z);
            float2 f3 = __half22float2(*(const __half2*)&raw.w);
            acc[0] = fmaf(pj, f0.x, acc[0]);
            acc[1] = fmaf(pj, f0.y, acc[1]);
            acc[2] = fmaf(pj, f1.x, acc[2]);
            acc[3] = fmaf(pj, f1.y, acc[3]);
            acc[4] = fmaf(pj, f2.x, acc[4]);
            acc[5] = fmaf(pj, f2.y, acc[5]);
            acc[6] = fmaf(pj, f3.x, acc[6]);
            acc[7] = fmaf(pj, f3.y, acc[7]);
        }
    }
#pragma unroll
    for (int o = 16; o; o >>= 1) {
        z += __shfl_xor_sync(0xffffffffu, z, o);
        cs += __shfl_xor_sync(0xffffffffu, cs, o);
    }
#pragma unroll
    for (int t = 0; t < 8; t++) {
        acc[t] += __shfl_xor_sync(~0u, acc[t], 8);
        acc[t] += __shfl_xor_sync(~0u, acc[t], 16);
    }
    int deg = end - beg;
    float eloop = cs / fmaxf((float)deg, 1.f);
    float al = g_hs[node] + hd_d + eloop;
    al = (al > 0.f) ? al : 0.2f * al;
    float pl = __expf(al);
    z += pl;
    {
        uint4 raw = *(const uint4*)(hbase + ((size_t)node << 6) + (sub << 3));
        float2 f0 = __half22float2(*(const __half2*)&raw.x);
        float2 f1 = __half22float2(*(const __half2*)&raw.y);
        float2 f2 = __half22float2(*(const __half2*)&raw.z);
        float2 f3 = __half22float2(*(const __half2*)&raw.w);
        acc[0] = fmaf(pl, f0.x, acc[0]);
        acc[1] = fmaf(pl, f0.y, acc[1]);
        acc[2] = fmaf(pl, f1.x, acc[2]);
        acc[3] = fmaf(pl, f1.y, acc[3]);
        acc[4] = fmaf(pl, f2.x, acc[4]);
        acc[5] = fmaf(pl, f2.y, acc[5]);
        acc[6] = fmaf(pl, f3.x, acc[6]);
        acc[7] = fmaf(pl, f3.y, acc[7]);
    }
    float inv = 1.f / z;
    float fv[8];
#pragma unroll
    for (int t = 0; t < 8; t++)
        fv[t] = fmaxf(fmaf(acc[t], inv, b[8 * sub + t]), 0.f);

    if (!FUSE) {
        if (lane < 8) {
            float4* fp = (float4*)(g_feat + (size_t)node * HH + 8 * sub);
            fp[0] = make_float4(fv[0], fv[1], fv[2], fv[3]);
            fp[1] = make_float4(fv[4], fv[5], fv[6], fv[7]);
        }
    } else {
        float accm = bc1[lane];
#pragma unroll
        for (int k = 0; k < 64; k++)
            accm = fmaf(__shfl_sync(~0u, fv[k & 7], k >> 3), Wc1[k * 32 + lane], accm);
        float hid = fmaxf(accm, 0.f);
        float lg = bc2[lane];
#pragma unroll
        for (int jj = 0; jj < 32; jj++)
            lg = fmaf(__shfl_sync(~0u, hid, jj), Wc2[jj * TT + lane], lg);
        out[(size_t)node * TT + lane] = lg;
    }
}

extern "C" void kernel_launch(void* const* d_in, const int* in_sizes, int n_in,
                              void* d_out, int out_size) {
    const float* x   = (const float*)d_in[0];
    const int*   ei  = (const int*)d_in[1];
    const float* ea  = (const float*)d_in[2];
    const float* W1  = (const float*)d_in[3];
    const float* as1 = (const float*)d_in[4];
    const float* ad1 = (const float*)d_in[5];
    const float* We1 = (const float*)d_in[6];
    const float* ae1 = (const float*)d_in[7];
    const float* b1  = (const float*)d_in[8];
    const float* W2  = (const float*)d_in[9];
    const float* as2 = (const float*)d_in[10];
    const float* ad2 = (const float*)d_in[11];
    const float* We2 = (const float*)d_in[12];
    const float* ae2 = (const float*)d_in[13];
    const float* b2  = (const float*)d_in[14];
    const float* Wc1 = (const float*)d_in[15];
    const float* bc1 = (const float*)d_in[16];
    const float* Wc2 = (const float*)d_in[17];
    const float* bc2 = (const float*)d_in[18];
    float* out = (float*)d_out;

    const int* src = ei;
    const int* dst = ei + NE;

    float* d_feat;
    cudaGetSymbolAddress((void**)&d_feat, g_feat);

    static cudaStream_t s2 = nullptr;
    static cudaEvent_t evFork = nullptr, evJoin = nullptr;
    if (!s2) {
        cudaStreamCreateWithFlags(&s2, cudaStreamNonBlocking);
        cudaEventCreateWithFlags(&evFork, cudaEventDisableTiming);
        cudaEventCreateWithFlags(&evJoin, cudaEventDisableTiming);
    }

    cudaEventRecord(evFork, 0);
    cudaStreamWaitEvent(s2, evFork, 0);

    k_init<<<(NN + 255) / 256, 256>>>(We1, ae1, We2, ae2);   // 1
    k_deg<<<(NE + 255) / 256, 256>>>(dst);                   // 2
    k_scan_lb<<<NBLK, SCAN_B>>>();                           // 3
    k_edge_pre<<<(NE + 255) / 256, 256>>>(ea, src, dst);     // 4  <- PROFILED

    k_gemm<FIN><<<(NN + 63) / 64, 256, 0, s2>>>(x, W1, as1, ad1);  // 5 (overlaps 1-4)
    cudaEventRecord(evJoin, s2);
    cudaStreamWaitEvent(0, evJoin, 0);

    // ---- layer 1 (agg launched TWICE: idempotent; delta = exact agg1 cost) ----
    k_aggregate<0, false><<<(NN + 7) / 8, 256>>>(b1, nullptr, nullptr, nullptr, nullptr, nullptr);  // 6
    k_aggregate<0, false><<<(NN + 7) / 8, 256>>>(b1, nullptr, nullptr, nullptr, nullptr, nullptr);  // 7 (probe)

    // ---- layer 2 (+ fused classifier) ----
    k_gemm<HH><<<(NN + 63) / 64, 256>>>(d_feat, W2, as2, ad2);                                      // 8
    k_aggregate<1, true><<<(NN + 7) / 8, 256>>>(b2, Wc1, bc1, Wc2, bc2, out);                       // 9
}

// round 14
// speedup vs baseline: 1.3954x; 1.3839x over previous
#include <cuda_runtime.h>
#include <cuda_fp16.h>
#include <stdint.h>
#include <math.h>

#define NN 100000
#define NE 1600000
#define FIN 128
#define FE 16
#define HH 64
#define TT 32
#define SCAN_B 1024
#define NBLK ((NN + SCAN_B - 1) / SCAN_B)   // 98

// ---------------- scratch (device globals; no runtime alloc) ----------------
__device__ __align__(16) __half2 g_h16[NN * 32];   // h in fp16, 64 halves/node
__device__ __align__(16) __half  g_feat16[NN * HH];// layer-1 output (relu'd, fp16)
__device__ float g_hs[NN];
__device__ float g_hd[NN];
__device__ int   g_degi[NN];
__device__ int   g_row[NN + 1];
__device__ int   g_cursor[NN];
__device__ volatile int g_bpub[NBLK];
__device__ __align__(16) int4 g_ecsr[NE];          // {src, cet0, cet1, pad}
__device__ float g_weae[2][FE];

__global__ void k_init(const float* We1, const float* ae1,
                       const float* We2, const float* ae2) {
    int idx = blockIdx.x * blockDim.x + threadIdx.x;
    if (idx < NN) g_degi[idx] = 0;
    if (idx < NBLK) g_bpub[idx] = 0;
    if (idx == 0) g_row[NN] = NE;
    if (blockIdx.x == 0) {
        int t = threadIdx.x;
        if (t < FE) {
            float s = 0.f;
            for (int h = 0; h < HH; h++) s += We1[t * HH + h] * ae1[h];
            g_weae[0][t] = s;
        } else if (t < 2 * FE) {
            int f = t - FE;
            float s = 0.f;
            for (int h = 0; h < HH; h++) s += We2[f * HH + h] * ae2[h];
            g_weae[1][f] = s;
        }
    }
}

__global__ void k_deg(const int* __restrict__ dst) {
    int e = blockIdx.x * blockDim.x + threadIdx.x;
    if (e < NE) atomicAdd(&g_degi[dst[e]], 1);
}

// single-kernel decoupled-lookback scan (98 blocks, all co-resident)
__global__ void k_scan_lb() {
    __shared__ int wsum[32];
    __shared__ int svals[NBLK];
    __shared__ int prevsum;
    int tid = threadIdx.x, lane = tid & 31, wid = tid >> 5;
    int b = blockIdx.x;
    int idx = b * SCAN_B + tid;
    int v = (idx < NN) ? g_degi[idx] : 0;
    int x = v;
#pragma unroll
    for (int o = 1; o < 32; o <<= 1) { int y = __shfl_up_sync(~0u, x, o); if (lane >= o) x += y; }
    if (lane == 31) wsum[wid] = x;
    __syncthreads();
    if (wid == 0) {
        int s = wsum[lane];
#pragma unroll
        for (int o = 1; o < 32; o <<= 1) { int y = __shfl_up_sync(~0u, s, o); if (lane >= o) s += y; }
        wsum[lane] = s;
    }
    __syncthreads();
    int off = wid ? wsum[wid - 1] : 0;
    if (tid == SCAN_B - 1) atomicExch((int*)&g_bpub[b], off + x + 1);
    if (tid < b) {
        int vv;
        do { vv = g_bpub[tid]; } while (vv == 0);
        svals[tid] = vv - 1;
    }
    __syncthreads();
    if (tid == 0) {
        int s = 0;
        for (int i = 0; i < b; i++) s += svals[i];
        prevsum = s;
    }
    __syncthreads();
    if (idx < NN) {
        int r = x - v + off + prevsum;
        g_row[idx] = r;
        g_cursor[idx] = r;
    }
}

__global__ void k_edge_pre(const float* __restrict__ ea, const int* __restrict__ src,
                           const int* __restrict__ dst) {
    int e = blockIdx.x * blockDim.x + threadIdx.x;
    if (e >= NE) return;
    int d = dst[e];
    const float4* v = (const float4*)(ea + (size_t)e * FE);
    float4 a0 = v[0], a1 = v[1], a2 = v[2], a3 = v[3];
    float av[16] = {a0.x, a0.y, a0.z, a0.w, a1.x, a1.y, a1.z, a1.w,
                    a2.x, a2.y, a2.z, a2.w, a3.x, a3.y, a3.z, a3.w};
    float s0 = 0.f, s1 = 0.f;
#pragma unroll
    for (int f = 0; f < FE; f++) {
        s0 += av[f] * g_weae[0][f];
        s1 += av[f] * g_weae[1][f];
    }
    int pos = atomicAdd(&g_cursor[d], 1);
    int4 ent;
    ent.x = src[e];
    ent.y = __float_as_int(s0);
    ent.z = __float_as_int(s1);
    ent.w = 0;
    g_ecsr[pos] = ent;
}

// ---------------- tensor-core GEMM: h = x @ W (fp16 mma, fp32 accum) --------
// 64x64 tile, 8 warps, each warp 16x32 via mma.m16n8k16. Epilogue in reused
// smem computes hs/hd dots and writes g_h16 (+ g_hs/g_hd).
template <int DIN, bool FP16IN>
__global__ __launch_bounds__(256) void k_gemm_mma(const float* __restrict__ xf,
                                                  const __half* __restrict__ xh,
                                                  const float* __restrict__ W,
                                                  const float* __restrict__ a_s,
                                                  const float* __restrict__ a_d) {
    constexpr int AS = DIN + 8;                       // padded half stride
    constexpr int STAGE_BYTES = 2 * 64 * AS * 2;
    constexpr int HT_BYTES = 64 * 66 * 4;
    constexpr int SBYTES = STAGE_BYTES > HT_BYTES ? STAGE_BYTES : HT_BYTES;
    __shared__ __align__(16) char smem[SBYTES];
    __half* xs = (__half*)smem;                       // [64][AS]
    __half* Wt = (__half*)(smem + 64 * AS * 2);       // [64][AS]  (n-major)
    float* ht = (float*)smem;                         // [64][66]  (reused)

    int tid = threadIdx.x;
    int lane = tid & 31;
    int wid = tid >> 5;
    int row0 = blockIdx.x * 64;

    // stage A (x rows -> fp16)
    if (FP16IN) {
        for (int i = tid; i < 64 * DIN / 2; i += 256) {
            int row = i / (DIN / 2);
            int k = 2 * (i % (DIN / 2));
            int rr = row0 + row;
            __half2 v = (rr < NN) ? *(const __half2*)(xh + (size_t)rr * DIN + k)
                                  : __floats2half2_rn(0.f, 0.f);
            *(__half2*)&xs[row * AS + k] = v;
        }
    } else {
        for (int i = tid; i < 64 * DIN / 2; i += 256) {
            int row = i / (DIN / 2);
            int k = 2 * (i % (DIN / 2));
            int rr = row0 + row;
            float2 v = (rr < NN) ? *(const float2*)(xf + (size_t)rr * DIN + k)
                                 : make_float2(0.f, 0.f);
            *(__half2*)&xs[row * AS + k] = __floats2half2_rn(v.x, v.y);
        }
    }
    // stage B transposed: Wt[n][k] = W[k][n]
    for (int i = tid; i < 64 * DIN / 2; i += 256) {
        int n = i & 63;
        int kk = i >> 6;
        float w0 = W[(2 * kk) * 64 + n];
        float w1 = W[(2 * kk + 1) * 64 + n];
        *(__half2*)&Wt[n * AS + 2 * kk] = __floats2half2_rn(w0, w1);
    }
    __syncthreads();

    int wm = (wid & 3) * 16;
    int wn = (wid >> 2) * 32;
    float c[4][4] = {};
    int r0 = wm + (lane >> 2);
    int kq = 2 * (lane & 3);
#pragma unroll
    for (int kc = 0; kc < DIN; kc += 16) {
        int k0 = kc + kq;
        unsigned int a0 = *(const unsigned int*)&xs[r0 * AS + k0];
        unsigned int a1 = *(const unsigned int*)&xs[(r0 + 8) * AS + k0];
        unsigned int a2 = *(const unsigned int*)&xs[r0 * AS + k0 + 8];
        unsigned int a3 = *(const unsigned int*)&xs[(r0 + 8) * AS + k0 + 8];
#pragma unroll
        for (int nt = 0; nt < 4; nt++) {
            int n0 = wn + nt * 8 + (lane >> 2);
            unsigned int b0 = *(const unsigned int*)&Wt[n0 * AS + k0];
            unsigned int b1 = *(const unsigned int*)&Wt[n0 * AS + k0 + 8];
            asm volatile(
                "mma.sync.aligned.m16n8k16.row.col.f32.f16.f16.f32 "
                "{%0,%1,%2,%3}, {%4,%5,%6,%7}, {%8,%9}, {%0,%1,%2,%3};"
                : "+f"(c[nt][0]), "+f"(c[nt][1]), "+f"(c[nt][2]), "+f"(c[nt][3])
                : "r"(a0), "r"(a1), "r"(a2), "r"(a3), "r"(b0), "r"(b1));
        }
    }
    __syncthreads();   // staging reads done; smem can be reused

    // store C frags to ht[64][66]
#pragma unroll
    for (int nt = 0; nt < 4; nt++) {
        int col = wn + nt * 8 + 2 * (lane & 3);
        int rr = wm + (lane >> 2);
        *(float2*)&ht[rr * 66 + col] = make_float2(c[nt][0], c[nt][1]);
        *(float2*)&ht[(rr + 8) * 66 + col] = make_float2(c[nt][2], c[nt][3]);
    }
    __syncthreads();

    // epilogue: warp w handles rows 8w..8w+7
    float as0 = a_s[lane], as1 = a_s[lane + 32];
    float ad0 = a_d[lane], ad1 = a_d[lane + 32];
#pragma unroll
    for (int rr = 0; rr < 8; rr++) {
        int r = wid * 8 + rr;
        int row = row0 + r;
        float h0 = ht[r * 66 + lane];
        float h1 = ht[r * 66 + 32 + lane];
        float ps = h0 * as0 + h1 * as1;
        float pd = h0 * ad0 + h1 * ad1;
#pragma unroll
        for (int o = 16; o; o >>= 1) {
            ps += __shfl_xor_sync(~0u, ps, o);
            pd += __shfl_xor_sync(~0u, pd, o);
        }
        if (row < NN) {
            if (lane == 0) { g_hs[row] = ps; g_hd[row] = pd; }
            float2 fr = *(const float2*)&ht[r * 66 + 2 * lane];
            g_h16[(size_t)row * 32 + lane] = __floats2half2_rn(fr.x, fr.y);
        }
    }
}

// One warp per dst node (R8-verified config). feat output now fp16.
template <int L, bool FUSE>
__global__ __launch_bounds__(256) void k_aggregate(const float* __restrict__ b,
                                                   const float* __restrict__ Wc1,
                                                   const float* __restrict__ bc1,
                                                   const float* __restrict__ Wc2,
                                                   const float* __restrict__ bc2,
                                                   float* __restrict__ out) {
    int node = blockIdx.x * 8 + (threadIdx.x >> 5);
    int lane = threadIdx.x & 31;
    if (node >= NN) return;
    int beg = g_row[node], end = g_row[node + 1];
    float hd_d = g_hd[node];
    int q = lane >> 3;
    int sub = lane & 7;
    const __half* hbase = (const __half*)g_h16;
    float acc[8] = {};
    float z = 0.f, cs = 0.f;

    for (int base = beg; base < end; base += 32) {
        int i = base + lane;
        bool valid = i < end;
        int4 ent = valid ? g_ecsr[i] : make_int4(0, 0, 0, 0);
        int s = ent.x;
        float c = __int_as_float((L == 0) ? ent.y : ent.z);
        float p = 0.f;
        if (valid) {
            float a = g_hs[s] + hd_d + c;
            a = (a > 0.f) ? a : 0.2f * a;
            p = __expf(a);
            z += p;
            cs += c;
        }
        int cnt = min(32, end - base);
        for (int j = 0; j < cnt; j += 4) {
            int idx = j + q;
            bool vq = idx < cnt;
            int sel = vq ? idx : 0;
            int sj = __shfl_sync(~0u, s, sel);
            float pj = __shfl_sync(~0u, p, sel);
            if (!vq) pj = 0.f;
            uint4 raw = *(const uint4*)(hbase + ((size_t)sj << 6) + (sub << 3));
            float2 f0 = __half22float2(*(const __half2*)&raw.x);
            float2 f1 = __half22float2(*(const __half2*)&raw.y);
            float2 f2 = __half22float2(*(const __half2*)&raw.z);
            float2 f3 = __half22float2(*(const __half2*)&raw.w);
            acc[0] = fmaf(pj, f0.x, acc[0]);
            acc[1] = fmaf(pj, f0.y, acc[1]);
            acc[2] = fmaf(pj, f1.x, acc[2]);
            acc[3] = fmaf(pj, f1.y, acc[3]);
            acc[4] = fmaf(pj, f2.x, acc[4]);
            acc[5] = fmaf(pj, f2.y, acc[5]);
            acc[6] = fmaf(pj, f3.x, acc[6]);
            acc[7] = fmaf(pj, f3.y, acc[7]);
        }
    }
#pragma unroll
    for (int o = 16; o; o >>= 1) {
        z += __shfl_xor_sync(0xffffffffu, z, o);
        cs += __shfl_xor_sync(0xffffffffu, cs, o);
    }
#pragma unroll
    for (int t = 0; t < 8; t++) {
        acc[t] += __shfl_xor_sync(~0u, acc[t], 8);
        acc[t] += __shfl_xor_sync(~0u, acc[t], 16);
    }
    int deg = end - beg;
    float eloop = cs / fmaxf((float)deg, 1.f);
    float al = g_hs[node] + hd_d + eloop;
    al = (al > 0.f) ? al : 0.2f * al;
    float pl = __expf(al);
    z += pl;
    {
        uint4 raw = *(const uint4*)(hbase + ((size_t)node << 6) + (sub << 3));
        float2 f0 = __half22float2(*(const __half2*)&raw.x);
        float2 f1 = __half22float2(*(const __half2*)&raw.y);
        float2 f2 = __half22float2(*(const __half2*)&raw.z);
        float2 f3 = __half22float2(*(const __half2*)&raw.w);
        acc[0] = fmaf(pl, f0.x, acc[0]);
        acc[1] = fmaf(pl, f0.y, acc[1]);
        acc[2] = fmaf(pl, f1.x, acc[2]);
        acc[3] = fmaf(pl, f1.y, acc[3]);
        acc[4] = fmaf(pl, f2.x, acc[4]);
        acc[5] = fmaf(pl, f2.y, acc[5]);
        acc[6] = fmaf(pl, f3.x, acc[6]);
        acc[7] = fmaf(pl, f3.y, acc[7]);
    }
    float inv = 1.f / z;
    float fv[8];
#pragma unroll
    for (int t = 0; t < 8; t++)
        fv[t] = fmaxf(fmaf(acc[t], inv, b[8 * sub + t]), 0.f);

    if (!FUSE) {
        if (lane < 8) {
            __half2 h01 = __floats2half2_rn(fv[0], fv[1]);
            __half2 h23 = __floats2half2_rn(fv[2], fv[3]);
            __half2 h45 = __floats2half2_rn(fv[4], fv[5]);
            __half2 h67 = __floats2half2_rn(fv[6], fv[7]);
            uint4 pk;
            pk.x = *(unsigned int*)&h01;
            pk.y = *(unsigned int*)&h23;
            pk.z = *(unsigned int*)&h45;
            pk.w = *(unsigned int*)&h67;
            *(uint4*)(g_feat16 + (size_t)node * HH + 8 * sub) = pk;
        }
    } else {
        float accm = bc1[lane];
#pragma unroll
        for (int k = 0; k < 64; k++)
            accm = fmaf(__shfl_sync(~0u, fv[k & 7], k >> 3), Wc1[k * 32 + lane], accm);
        float hid = fmaxf(accm, 0.f);
        float lg = bc2[lane];
#pragma unroll
        for (int jj = 0; jj < 32; jj++)
            lg = fmaf(__shfl_sync(~0u, hid, jj), Wc2[jj * TT + lane], lg);
        out[(size_t)node * TT + lane] = lg;
    }
}

extern "C" void kernel_launch(void* const* d_in, const int* in_sizes, int n_in,
                              void* d_out, int out_size) {
    const float* x   = (const float*)d_in[0];
    const int*   ei  = (const int*)d_in[1];
    const float* ea  = (const float*)d_in[2];
    const float* W1  = (const float*)d_in[3];
    const float* as1 = (const float*)d_in[4];
    const float* ad1 = (const float*)d_in[5];
    const float* We1 = (const float*)d_in[6];
    const float* ae1 = (const float*)d_in[7];
    const float* b1  = (const float*)d_in[8];
    const float* W2  = (const float*)d_in[9];
    const float* as2 = (const float*)d_in[10];
    const float* ad2 = (const float*)d_in[11];
    const float* We2 = (const float*)d_in[12];
    const float* ae2 = (const float*)d_in[13];
    const float* b2  = (const float*)d_in[14];
    const float* Wc1 = (const float*)d_in[15];
    const float* bc1 = (const float*)d_in[16];
    const float* Wc2 = (const float*)d_in[17];
    const float* bc2 = (const float*)d_in[18];
    float* out = (float*)d_out;

    const int* src = ei;
    const int* dst = ei + NE;

    __half* d_feat16;
    cudaGetSymbolAddress((void**)&d_feat16, g_feat16);

    static cudaStream_t s2 = nullptr;
    static cudaEvent_t evFork = nullptr, evJoin = nullptr;
    if (!s2) {
        cudaStreamCreateWithFlags(&s2, cudaStreamNonBlocking);
        cudaEventCreateWithFlags(&evFork, cudaEventDisableTiming);
        cudaEventCreateWithFlags(&evJoin, cudaEventDisableTiming);
    }

    cudaEventRecord(evFork, 0);
    cudaStreamWaitEvent(s2, evFork, 0);

    k_init<<<(NN + 255) / 256, 256>>>(We1, ae1, We2, ae2);   // 1
    k_deg<<<(NE + 255) / 256, 256>>>(dst);                   // 2
    k_scan_lb<<<NBLK, SCAN_B>>>();                           // 3
    k_gemm_mma<FIN, false><<<(NN + 63) / 64, 256, 0, s2>>>(x, nullptr, W1, as1, ad1);  // 4 <- PROFILED
    cudaEventRecord(evJoin, s2);
    k_edge_pre<<<(NE + 255) / 256, 256>>>(ea, src, dst);     // 5

    cudaStreamWaitEvent(0, evJoin, 0);

    // ---- layer 1 ----
    k_aggregate<0, false><<<(NN + 7) / 8, 256>>>(b1, nullptr, nullptr, nullptr, nullptr, nullptr);

    // ---- layer 2 (+ fused classifier) ----
    k_gemm_mma<HH, true><<<(NN + 63) / 64, 256>>>(nullptr, d_feat16, W2, as2, ad2);
    k_aggregate<1, true><<<(NN + 7) / 8, 256>>>(b2, Wc1, bc1, Wc2, bc2, out);
}